// round 16
// baseline (speedup 1.0000x reference)
#include <cuda_runtime.h>
#include <cstdint>

#define BATCH  8
#define HWDIM  64
#define CCH    256
#define RED    64
#define EE     144     // K*K*G = 9*16
#define NTHR   256

// ---- smem layout (32-bit word offsets), tile 8x4 ----
#define HALO_W     6
#define XH_STRIDE  260
#define OFF_XH     0                    // 60*260 = 15600 (fp32 halo)
#define OFF_MID    15600                // 32*68 = 2176
#define MID_STRIDE 68
#define OFF_STREAM 17776                // 6912 words (W1: 2x2560, W2: 2x3456)
#define OFF_WGT    17776                // overlay stream buffer after stage2: 32*145=4640
#define WGT_STRIDE 145
#define OFF_B1     24688                // 64
#define OFF_B2     24752                // 144
#define SMEM_WORDS 24896
#define SMEM_BYTES (SMEM_WORDS * 4)     // 99584 B -> 2 CTAs/SM

// gmem weight planes (built by prep kernel)
__device__ uint32_t g_w1p[16384];       // [c(8)][plane(2)][n(64)][16]
__device__ uint32_t g_w2p[9216];        // [s(4)][plane(2)][e(144)][8]

__device__ __forceinline__ void mma_bf16(float d[4],
    uint32_t a0, uint32_t a1, uint32_t a2, uint32_t a3,
    uint32_t b0, uint32_t b1)
{
    asm volatile(
        "mma.sync.aligned.m16n8k16.row.col.f32.bf16.bf16.f32 "
        "{%0,%1,%2,%3}, {%4,%5,%6,%7}, {%8,%9}, {%0,%1,%2,%3};"
        : "+f"(d[0]), "+f"(d[1]), "+f"(d[2]), "+f"(d[3])
        : "r"(a0), "r"(a1), "r"(a2), "r"(a3), "r"(b0), "r"(b1));
}

__device__ __forceinline__ void bf16_split_pair(float v0, float v1,
                                                uint32_t& hi, uint32_t& lo)
{
    uint32_t h;
    asm("cvt.rn.bf16x2.f32 %0, %1, %2;" : "=r"(h) : "f"(v1), "f"(v0));
    float h0 = __uint_as_float(h << 16);
    float h1 = __uint_as_float(h & 0xFFFF0000u);
    float l0 = v0 - h0;
    float l1 = v1 - h1;
    asm("cvt.rn.bf16x2.f32 %0, %1, %2;" : "=r"(lo) : "f"(l1), "f"(l0));
    hi = h;
}

__device__ __forceinline__ void cp_async16(uint32_t daddr, const void* src, int sz)
{
    asm volatile("cp.async.cg.shared.global [%0], [%1], 16, %2;"
                 :: "r"(daddr), "l"(src), "r"(sz));
}
#define CP_COMMIT() asm volatile("cp.async.commit_group;" ::: "memory")
#define CP_WAIT(n)  asm volatile("cp.async.wait_group %0;" :: "n"(n) : "memory")

// ============ prep: build bf16 hi/lo weight planes in gmem ============
__global__ void prep_kernel(const float* __restrict__ W1, const float* __restrict__ W2)
{
    int i = blockIdx.x * 256 + threadIdx.x;
    if (i < 8192) {                        // W1 unit (c, n, w)
        int w = i & 15, cn = i >> 4;
        int n = cn & 63, c = cn >> 6;
        int s  = c * 2 + (w >> 3);
        int kp = s * 8 + (w & 7);
        uint32_t h, l;
        bf16_split_pair(W1[(kp * 2) * RED + n], W1[(kp * 2 + 1) * RED + n], h, l);
        g_w1p[((c * 2 + 0) * 64 + n) * 16 + w] = h;
        g_w1p[((c * 2 + 1) * 64 + n) * 16 + w] = l;
    } else {
        int j = i - 8192;
        if (j < 4608) {                    // W2 unit (s, e, w)
            int w = j & 7, se = j >> 3;
            int e = se % 144, ss = se / 144;
            int kp = ss * 8 + w;
            uint32_t h, l;
            bf16_split_pair(W2[(kp * 2) * EE + e], W2[(kp * 2 + 1) * EE + e], h, l);
            g_w2p[((ss * 2 + 0) * 144 + e) * 8 + w] = h;
            g_w2p[((ss * 2 + 1) * 144 + e) * 8 + w] = l;
        }
    }
}

// ============ fused kernel, tile 8x4, 2 CTAs/SM ============
__global__ void __launch_bounds__(NTHR, 2)
invo_mma_kernel(const float* __restrict__ x,
                const float* __restrict__ b1,
                const float* __restrict__ b2,
                float* __restrict__ out)
{
    extern __shared__ float s[];
    uint32_t* su = (uint32_t*)s;
    const int t  = threadIdx.x;
    const int bb = blockIdx.z;
    const int h0 = blockIdx.y * 8;
    const int w0 = blockIdx.x * 4;

    uint32_t s_base;
    asm("{ .reg .u64 tt; cvta.to.shared.u64 tt, %1; cvt.u32.u64 %0, tt; }"
        : "=r"(s_base) : "l"(s));

    // ---- Phase 0: halo 10x6x256 via cp.async (zero-fill OOB) ----
    #pragma unroll
    for (int it = 0; it < 15; it++) {
        int i4 = t + it * NTHR;            // 0..3839 float4s
        int c4 = i4 & 63;
        int sp = i4 >> 6;                  // 0..59
        int r  = sp / HALO_W;
        int cl = sp - r * HALO_W;
        int gh = h0 - 1 + r;
        int gw = w0 - 1 + cl;
        bool ok = ((unsigned)gh < HWDIM) && ((unsigned)gw < HWDIM);
        const float* gp = ok
            ? x + ((size_t)((bb * HWDIM + gh) * HWDIM + gw) * CCH) + c4 * 4
            : x;
        cp_async16(s_base + (OFF_XH + sp * XH_STRIDE + c4 * 4) * 4, gp, ok ? 16 : 0);
    }
    // W1 chunk 0 -> stream buf 0 ([plane][n][20], 16 words used per n)
    #pragma unroll
    for (int it = 0; it < 2; it++) {
        int u = t + it * NTHR;             // 0..511
        int w4 = u & 3, n = (u >> 2) & 63, p = u >> 8;
        cp_async16(s_base + (OFF_STREAM + p * 1280 + n * 20 + w4 * 4) * 4,
                   g_w1p + (p * 64 + n) * 16 + w4 * 4, 16);
    }
    CP_COMMIT();

    if (t < RED) s[OFF_B1 + t] = b1[t];
    else if (t >= 112 && t < 112 + EE) s[OFF_B2 + (t - 112)] = b2[t - 112];

    CP_WAIT(0);
    __syncthreads();

    const int warp = t >> 5, lane = t & 31;
    const int gid = lane >> 2, t4 = lane & 3;

    // ---- Stage 1: mid[32px][64] = x @ W1 + b1 (streamed B, 8 chunks x 2 steps) ----
    // 8 warps: mt = warp>>2 (m-tile of 16), nq = warp&3 (2 ntiles)
    {
        const int mt = warp >> 2;
        const int nq = warp & 3;
        const int m0 = mt * 16;
        const int px0 = m0 + gid, px1 = px0 + 8;
        const int sp0 = OFF_XH + (((px0 >> 2) + 1) * HALO_W + (px0 & 3) + 1) * XH_STRIDE;
        const int sp1 = OFF_XH + (((px1 >> 2) + 1) * HALO_W + (px1 & 3) + 1) * XH_STRIDE;
        float Dm[2][4], Dc[2][4];
        #pragma unroll
        for (int nt = 0; nt < 2; nt++)
            #pragma unroll
            for (int i = 0; i < 4; i++) { Dm[nt][i] = 0.f; Dc[nt][i] = 0.f; }

        for (int c = 0; c < 8; c++) {
            if (c < 7) {                   // prefetch chunk c+1
                int cb = (c + 1) & 1;
                #pragma unroll
                for (int it = 0; it < 2; it++) {
                    int u = t + it * NTHR;
                    int w4 = u & 3, n = (u >> 2) & 63, p = u >> 8;
                    cp_async16(s_base + (OFF_STREAM + cb * 2560 + p * 1280 + n * 20 + w4 * 4) * 4,
                               g_w1p + ((c + 1) * 2 + p) * 1024 + (n * 16) + w4 * 4, 16);
                }
                CP_COMMIT();
            }
            const int cb = c & 1;
            #pragma unroll
            for (int q = 0; q < 2; q++) {  // 2 k16-steps per chunk
                const int k0 = (c * 2 + q) * 16;
                float2 p0 = *(const float2*)(s + sp0 + k0 + 2 * t4);
                float2 p1 = *(const float2*)(s + sp1 + k0 + 2 * t4);
                float2 p2 = *(const float2*)(s + sp0 + k0 + 8 + 2 * t4);
                float2 p3 = *(const float2*)(s + sp1 + k0 + 8 + 2 * t4);
                uint32_t ah[4], al[4];
                bf16_split_pair(p0.x, p0.y, ah[0], al[0]);
                bf16_split_pair(p1.x, p1.y, ah[1], al[1]);
                bf16_split_pair(p2.x, p2.y, ah[2], al[2]);
                bf16_split_pair(p3.x, p3.y, ah[3], al[3]);
                const int bw = OFF_STREAM + cb * 2560 + q * 8 + t4;
                #pragma unroll
                for (int nt = 0; nt < 2; nt++) {
                    int n = (nq * 2 + nt) * 8 + gid;
                    uint32_t bh0 = su[bw + n * 20];
                    uint32_t bh1 = su[bw + n * 20 + 4];
                    uint32_t bl0 = su[bw + 1280 + n * 20];
                    uint32_t bl1 = su[bw + 1280 + n * 20 + 4];
                    mma_bf16(Dm[nt], ah[0], ah[1], ah[2], ah[3], bh0, bh1);
                    mma_bf16(Dc[nt], al[0], al[1], al[2], al[3], bh0, bh1);
                    mma_bf16(Dc[nt], ah[0], ah[1], ah[2], ah[3], bl0, bl1);
                }
            }
            if (c < 7) { CP_WAIT(0); __syncthreads(); }
        }
        // epilogue -> mid fp32
        #pragma unroll
        for (int nt = 0; nt < 2; nt++) {
            int n0 = (nq * 2 + nt) * 8 + 2 * t4;
            float bia0 = s[OFF_B1 + n0], bia1 = s[OFF_B1 + n0 + 1];
            *(float2*)(s + OFF_MID + (m0 + gid) * MID_STRIDE + n0) =
                make_float2(Dm[nt][0] + Dc[nt][0] + bia0, Dm[nt][1] + Dc[nt][1] + bia1);
            *(float2*)(s + OFF_MID + (m0 + gid + 8) * MID_STRIDE + n0) =
                make_float2(Dm[nt][2] + Dc[nt][2] + bia0, Dm[nt][3] + Dc[nt][3] + bia1);
        }
    }
    __syncthreads();   // mid visible; W1 stream region free

    // ---- Stage 2: wgt[32px][144] = mid @ W2 + b2 (streamed B, 4 steps) ----
    {
        const int m0 = (warp >> 2) * 16;
        const int nset = warp & 3;
        float Dm[5][4], Dc[5][4];
        #pragma unroll
        for (int j = 0; j < 5; j++)
            #pragma unroll
            for (int i = 0; i < 4; i++) { Dm[j][i] = 0.f; Dc[j][i] = 0.f; }

        // prefetch step 0
        #pragma unroll
        for (int it = 0; it < 3; it++) {
            int u = t + it * NTHR;
            if (u < 576) {
                int w4 = u & 1, ep = u >> 1;
                int e = ep % 144, p = ep / 144;
                cp_async16(s_base + (OFF_STREAM + p * 1728 + e * 12 + w4 * 4) * 4,
                           g_w2p + p * 1152 + e * 8 + w4 * 4, 16);
            }
        }
        CP_COMMIT();
        CP_WAIT(0);
        __syncthreads();

        for (int sstep = 0; sstep < 4; sstep++) {
            if (sstep < 3) {               // prefetch step s+1
                int sb = (sstep + 1) & 1;
                #pragma unroll
                for (int it = 0; it < 3; it++) {
                    int u = t + it * NTHR;
                    if (u < 576) {
                        int w4 = u & 1, ep = u >> 1;
                        int e = ep % 144, p = ep / 144;
                        cp_async16(s_base + (OFF_STREAM + sb * 3456 + p * 1728 + e * 12 + w4 * 4) * 4,
                                   g_w2p + ((sstep + 1) * 2 + p) * 1152 + e * 8 + w4 * 4, 16);
                    }
                }
                CP_COMMIT();
            }
            const int sb = sstep & 1;
            const int k0 = sstep * 16;
            float2 q0 = *(const float2*)(s + OFF_MID + (m0 + gid)     * MID_STRIDE + k0 + 2 * t4);
            float2 q1 = *(const float2*)(s + OFF_MID + (m0 + gid + 8) * MID_STRIDE + k0 + 2 * t4);
            float2 q2 = *(const float2*)(s + OFF_MID + (m0 + gid)     * MID_STRIDE + k0 + 8 + 2 * t4);
            float2 q3 = *(const float2*)(s + OFF_MID + (m0 + gid + 8) * MID_STRIDE + k0 + 8 + 2 * t4);
            uint32_t ah[4], al[4];
            bf16_split_pair(q0.x, q0.y, ah[0], al[0]);
            bf16_split_pair(q1.x, q1.y, ah[1], al[1]);
            bf16_split_pair(q2.x, q2.y, ah[2], al[2]);
            bf16_split_pair(q3.x, q3.y, ah[3], al[3]);
            const int bw = OFF_STREAM + sb * 3456 + t4;
            #pragma unroll
            for (int jj = 0; jj < 5; jj++) {
                int j = nset + jj * 4;
                if (j < 18) {
                    int e = j * 8 + gid;
                    uint32_t bh0 = su[bw + e * 12];
                    uint32_t bh1 = su[bw + e * 12 + 4];
                    uint32_t bl0 = su[bw + 1728 + e * 12];
                    uint32_t bl1 = su[bw + 1728 + e * 12 + 4];
                    mma_bf16(Dm[jj], ah[0], ah[1], ah[2], ah[3], bh0, bh1);
                    mma_bf16(Dc[jj], al[0], al[1], al[2], al[3], bh0, bh1);
                    mma_bf16(Dc[jj], ah[0], ah[1], ah[2], ah[3], bl0, bl1);
                }
            }
            if (sstep < 3) { CP_WAIT(0); __syncthreads(); }
        }
        __syncthreads();   // stream buffer dead -> safe to overlay wgt
        #pragma unroll
        for (int jj = 0; jj < 5; jj++) {
            int j = nset + jj * 4;
            if (j < 18) {
                int e0 = j * 8 + 2 * t4;
                float bb0 = s[OFF_B2 + e0], bb1 = s[OFF_B2 + e0 + 1];
                s[OFF_WGT + (m0 + gid)     * WGT_STRIDE + e0]     = Dm[jj][0] + Dc[jj][0] + bb0;
                s[OFF_WGT + (m0 + gid)     * WGT_STRIDE + e0 + 1] = Dm[jj][1] + Dc[jj][1] + bb1;
                s[OFF_WGT + (m0 + gid + 8) * WGT_STRIDE + e0]     = Dm[jj][2] + Dc[jj][2] + bb0;
                s[OFF_WGT + (m0 + gid + 8) * WGT_STRIDE + e0 + 1] = Dm[jj][3] + Dc[jj][3] + bb1;
            }
        }
    }
    __syncthreads();

    // ---- Stage 3: involution (8 warps = tile rows; R12-validated mapping) ----
    {
        const int pr = warp;
        const int gset = lane >> 2, pc = lane & 3;
        const int wbase = OFF_WGT + (pr * 4 + pc) * WGT_STRIDE;
        const int xb = OFF_XH + (pr * HALO_W + pc) * XH_STRIDE;   // tap (0,0)
        float* op = out + ((size_t)((bb * HWDIM + h0 + pr) * HWDIM + (w0 + pc))) * CCH;
        #pragma unroll
        for (int gi = 0; gi < 2; gi++) {
            int g = gset * 2 + gi;
            float wv[9];
            #pragma unroll
            for (int k = 0; k < 9; k++) wv[k] = s[wbase + g * 9 + k];
            int F0g = g * 36;
            int ko0 = F0g >> 6;
            int cs0 = F0g & 63;
            int tc  = 64 - cs0;
            int di0 = (ko0 * 11) >> 5, dj0 = ko0 - 3 * di0;
            int ko1 = ko0 + 1;
            int di1 = (ko1 * 11) >> 5, dj1 = ko1 - 3 * di1;
            int A0 = xb + (di0 * HALO_W + dj0) * XH_STRIDE + cs0 * 4;
            int A1 = xb + (di1 * HALO_W + dj1) * XH_STRIDE - tc * 4;
            #pragma unroll
            for (int c = 0; c < 4; c++) {
                float acc[4] = {0.f, 0.f, 0.f, 0.f};
                #pragma unroll
                for (int j = 0; j < 9; j++) {
                    const int idx = c * 9 + j;
                    int addr = ((idx < tc) ? A0 : A1) + idx * 4;
                    const float4 xv = *(const float4*)(s + addr);
                    const int fl = idx * 4;
                    acc[(fl + 0) / 9 - c * 4] += wv[(fl + 0) % 9] * xv.x;
                    acc[(fl + 1) / 9 - c * 4] += wv[(fl + 1) % 9] * xv.y;
                    acc[(fl + 2) / 9 - c * 4] += wv[(fl + 2) % 9] * xv.z;
                    acc[(fl + 3) / 9 - c * 4] += wv[(fl + 3) % 9] * xv.w;
                }
                *(float4*)(op + g * 16 + c * 4) =
                    make_float4(acc[0], acc[1], acc[2], acc[3]);
            }
        }
    }
}

extern "C" void kernel_launch(void* const* d_in, const int* in_sizes, int n_in,
                              void* d_out, int out_size)
{
    (void)in_sizes; (void)n_in; (void)out_size;
    const float* x  = (const float*)d_in[0];
    const float* W1 = (const float*)d_in[1];
    const float* b1 = (const float*)d_in[2];
    const float* W2 = (const float*)d_in[3];
    const float* b2 = (const float*)d_in[4];
    float* out = (float*)d_out;

    cudaFuncSetAttribute(invo_mma_kernel,
                         cudaFuncAttributeMaxDynamicSharedMemorySize, SMEM_BYTES);
    prep_kernel<<<50, 256>>>(W1, W2);
    dim3 grid(HWDIM / 4, HWDIM / 8, BATCH);   // (16, 8, 8) = 1024 CTAs
    invo_mma_kernel<<<grid, NTHR, SMEM_BYTES>>>(x, b1, b2, out);
}

// round 17
// speedup vs baseline: 1.2218x; 1.2218x over previous
#include <cuda_runtime.h>
#include <cstdint>

#define BATCH  8
#define HWDIM  64
#define CCH    256
#define RED    64
#define EE     144     // K*K*G = 9*16
#define NTHR   512

// ---- smem layout (32-bit word offsets) ----
#define XH_STRIDE  260
#define OFF_XH     0                    // 100*260 = 26000 (fp32)
#define OFF_W1H    26000                // 64*132 = 8448 (bf16x2, [n][k/2])
#define W1P_STRIDE 132
#define OFF_W1L    34448                // 8448 ; planes end 42896
#define OFF_WGT    26000                // overlay W1 planes after stage1: 64*145 = 9280
#define WGT_STRIDE 145
#define OFF_W2H    42896                // 144*36 = 5184 ([e][d/2])
#define W2P_STRIDE 36
#define OFF_W2L    48080                // 5184 ; end 53264
#define OFF_MID    53264                // 64*68 = 4352 (fp32)
#define MID_STRIDE 68
#define OFF_B1     57616                // 64
#define OFF_B2     57680                // 144
#define SMEM_WORDS 57824
#define SMEM_BYTES (SMEM_WORDS * 4)     // 231296 B, 1 CTA/SM

// m16n8k16 bf16 mma
__device__ __forceinline__ void mma_bf16(float d[4],
    uint32_t a0, uint32_t a1, uint32_t a2, uint32_t a3,
    uint32_t b0, uint32_t b1)
{
    asm volatile(
        "mma.sync.aligned.m16n8k16.row.col.f32.bf16.bf16.f32 "
        "{%0,%1,%2,%3}, {%4,%5,%6,%7}, {%8,%9}, {%0,%1,%2,%3};"
        : "+f"(d[0]), "+f"(d[1]), "+f"(d[2]), "+f"(d[3])
        : "r"(a0), "r"(a1), "r"(a2), "r"(a3), "r"(b0), "r"(b1));
}

__device__ __forceinline__ void bf16_split_pair(float v0, float v1,
                                                uint32_t& hi, uint32_t& lo)
{
    uint32_t h;
    asm("cvt.rn.bf16x2.f32 %0, %1, %2;" : "=r"(h) : "f"(v1), "f"(v0));
    float h0 = __uint_as_float(h << 16);
    float h1 = __uint_as_float(h & 0xFFFF0000u);
    float l0 = v0 - h0;
    float l1 = v1 - h1;
    asm("cvt.rn.bf16x2.f32 %0, %1, %2;" : "=r"(lo) : "f"(l1), "f"(l0));
    hi = h;
}

__device__ __forceinline__ void cp_async16(uint32_t daddr, const void* src, int sz)
{
    asm volatile("cp.async.cg.shared.global [%0], [%1], 16, %2;"
                 :: "r"(daddr), "l"(src), "r"(sz));
}

__global__ void __launch_bounds__(NTHR, 1)
invo_mma_kernel(const float* __restrict__ x,
                const float* __restrict__ W1,
                const float* __restrict__ b1,
                const float* __restrict__ W2,
                const float* __restrict__ b2,
                float* __restrict__ out)
{
    extern __shared__ float s[];
    uint32_t* su = (uint32_t*)s;
    const int t  = threadIdx.x;
    const int bb = blockIdx.z;
    const int h0 = blockIdx.y * 8;
    const int w0 = blockIdx.x * 8;

    uint32_t s_base;
    asm("{ .reg .u64 tt; cvta.to.shared.u64 tt, %1; cvt.u32.u64 %0, tt; }"
        : "=r"(s_base) : "l"(s));

    // ---- Phase 0a-1: CENTER 8x8x256 via cp.async (always in-bounds) -> group 0 ----
    #pragma unroll
    for (int it = 0; it < 8; it++) {
        int i4 = t + it * NTHR;            // 0..4095
        int c4 = i4 & 63;
        int u  = i4 >> 6;                  // 0..63
        int r  = (u >> 3) + 1;
        int cl = (u & 7) + 1;
        int sp = r * 10 + cl;
        const float* gp = x + ((size_t)((bb * HWDIM + h0 + (u >> 3)) * HWDIM
                                        + (w0 + (u & 7))) * CCH) + c4 * 4;
        cp_async16(s_base + (OFF_XH + sp * XH_STRIDE + c4 * 4) * 4, gp, 16);
    }
    asm volatile("cp.async.commit_group;" ::: "memory");

    // ---- Phase 0a-2: RING 36 positions (zero-fill OOB) -> group 1 ----
    #pragma unroll
    for (int it = 0; it < 5; it++) {
        int i4 = t + it * NTHR;            // 0..2303
        if (i4 < 2304) {
            int c4 = i4 & 63;
            int p  = i4 >> 6;              // 0..35
            int r, cl;
            if (p < 10)      { r = 0; cl = p; }
            else if (p < 20) { r = 9; cl = p - 10; }
            else             { int q = p - 20; r = 1 + (q >> 1); cl = (q & 1) * 9; }
            int gh = h0 - 1 + r;
            int gw = w0 - 1 + cl;
            bool ok = ((unsigned)gh < HWDIM) && ((unsigned)gw < HWDIM);
            const float* gp = ok
                ? x + ((size_t)((bb * HWDIM + gh) * HWDIM + gw) * CCH) + c4 * 4
                : x;
            cp_async16(s_base + (OFF_XH + (r * 10 + cl) * XH_STRIDE + c4 * 4) * 4,
                       gp, ok ? 16 : 0);
        }
    }
    asm volatile("cp.async.commit_group;" ::: "memory");

    // ---- Phase 0b: W1 -> bf16 hi/lo planes [n][k/2] ----
    #pragma unroll
    for (int it = 0; it < 4; it++) {
        int u = t + it * NTHR;             // 2048 units: (n, k-octet)
        int n  = u & 63;
        int ko = u >> 6;                   // 0..31
        float v[8];
        #pragma unroll
        for (int j = 0; j < 8; j++) v[j] = W1[(ko * 8 + j) * RED + n];
        uint32_t h[4], l[4];
        #pragma unroll
        for (int p = 0; p < 4; p++) bf16_split_pair(v[2*p], v[2*p+1], h[p], l[p]);
        int base = n * W1P_STRIDE + ko * 4;
        *(uint4*)(su + OFF_W1H + base) = make_uint4(h[0], h[1], h[2], h[3]);
        *(uint4*)(su + OFF_W1L + base) = make_uint4(l[0], l[1], l[2], l[3]);
    }
    // ---- Phase 0c: W2 -> bf16 hi/lo planes [e][d/2] (1152 octet-units) ----
    #pragma unroll
    for (int it = 0; it < 3; it++) {
        int u = t + it * NTHR;
        if (u < 1152) {
            int dko = u / 144;             // 0..7
            int e   = u - dko * 144;
            float v[8];
            #pragma unroll
            for (int j = 0; j < 8; j++) v[j] = W2[(dko * 8 + j) * EE + e];
            uint32_t h[4], l[4];
            #pragma unroll
            for (int p = 0; p < 4; p++) bf16_split_pair(v[2*p], v[2*p+1], h[p], l[p]);
            int base = e * W2P_STRIDE + dko * 4;
            *(uint4*)(su + OFF_W2H + base) = make_uint4(h[0], h[1], h[2], h[3]);
            *(uint4*)(su + OFF_W2L + base) = make_uint4(l[0], l[1], l[2], l[3]);
        }
    }
    if (t < RED) s[OFF_B1 + t] = b1[t];
    else if (t >= 128 && t < 128 + EE) s[OFF_B2 + (t - 128)] = b2[t - 128];

    // wait for CENTER only (ring keeps flying behind stage 1)
    asm volatile("cp.async.wait_group 1;" ::: "memory");
    __syncthreads();

    const int warp = t >> 5, lane = t & 31;
    const int gid = lane >> 2, t4 = lane & 3;

    // ---- Stage 1: mid[64px][64] = x @ W1 + b1  (3-term bf16 k16, K-SPLIT) ----
    // 16 warps: mt = warp>>2 (m-tile), nh = (warp>>1)&1 (4 ntiles), kh = warp&1 (K half)
    {
        const int mt = warp >> 2;
        const int nh = (warp >> 1) & 1;
        const int kh = warp & 1;
        const int m0 = mt * 16;
        const int px0 = m0 + gid, px1 = px0 + 8;
        const int sp0 = OFF_XH + (((px0 >> 3) + 1) * 10 + (px0 & 7) + 1) * XH_STRIDE;
        const int sp1 = OFF_XH + (((px1 >> 3) + 1) * 10 + (px1 & 7) + 1) * XH_STRIDE;
        float Dm[4][4], Dc[4][4];
        #pragma unroll
        for (int j = 0; j < 4; j++)
            #pragma unroll
            for (int i = 0; i < 4; i++) { Dm[j][i] = 0.f; Dc[j][i] = 0.f; }

        #pragma unroll 4
        for (int ss = 0; ss < 8; ss++) {
            const int k0 = (kh * 8 + ss) * 16;
            float2 p0 = *(const float2*)(s + sp0 + k0 + 2 * t4);
            float2 p1 = *(const float2*)(s + sp1 + k0 + 2 * t4);
            float2 p2 = *(const float2*)(s + sp0 + k0 + 8 + 2 * t4);
            float2 p3 = *(const float2*)(s + sp1 + k0 + 8 + 2 * t4);
            uint32_t ah[4], al[4];
            bf16_split_pair(p0.x, p0.y, ah[0], al[0]);
            bf16_split_pair(p1.x, p1.y, ah[1], al[1]);
            bf16_split_pair(p2.x, p2.y, ah[2], al[2]);
            bf16_split_pair(p3.x, p3.y, ah[3], al[3]);
            const int kw = (k0 >> 1) + t4;
            #pragma unroll
            for (int jj = 0; jj < 4; jj++) {
                int n = (nh * 4 + jj) * 8 + gid;
                uint32_t bh0 = su[OFF_W1H + n * W1P_STRIDE + kw];
                uint32_t bh1 = su[OFF_W1H + n * W1P_STRIDE + kw + 4];
                uint32_t bl0 = su[OFF_W1L + n * W1P_STRIDE + kw];
                uint32_t bl1 = su[OFF_W1L + n * W1P_STRIDE + kw + 4];
                mma_bf16(Dm[jj], ah[0], ah[1], ah[2], ah[3], bh0, bh1);
                mma_bf16(Dc[jj], al[0], al[1], al[2], al[3], bh0, bh1);
                mma_bf16(Dc[jj], ah[0], ah[1], ah[2], ah[3], bl0, bl1);
            }
        }
        // reduction: kh=0 writes partial; per-QUAD named barrier; kh=1 adds + bias
        if (kh == 0) {
            #pragma unroll
            for (int jj = 0; jj < 4; jj++) {
                int n0 = (nh * 4 + jj) * 8 + 2 * t4;
                *(float2*)(s + OFF_MID + (m0 + gid) * MID_STRIDE + n0) =
                    make_float2(Dm[jj][0] + Dc[jj][0], Dm[jj][1] + Dc[jj][1]);
                *(float2*)(s + OFF_MID + (m0 + gid + 8) * MID_STRIDE + n0) =
                    make_float2(Dm[jj][2] + Dc[jj][2], Dm[jj][3] + Dc[jj][3]);
            }
        }
        asm volatile("bar.sync %0, 128;" :: "r"(4 + mt) : "memory");
        if (kh == 1) {
            #pragma unroll
            for (int jj = 0; jj < 4; jj++) {
                int n0 = (nh * 4 + jj) * 8 + 2 * t4;
                float bia0 = s[OFF_B1 + n0], bia1 = s[OFF_B1 + n0 + 1];
                float2 q0 = *(const float2*)(s + OFF_MID + (m0 + gid) * MID_STRIDE + n0);
                float2 q1 = *(const float2*)(s + OFF_MID + (m0 + gid + 8) * MID_STRIDE + n0);
                *(float2*)(s + OFF_MID + (m0 + gid) * MID_STRIDE + n0) =
                    make_float2(q0.x + Dm[jj][0] + Dc[jj][0] + bia0,
                                q0.y + Dm[jj][1] + Dc[jj][1] + bia1);
                *(float2*)(s + OFF_MID + (m0 + gid + 8) * MID_STRIDE + n0) =
                    make_float2(q1.x + Dm[jj][2] + Dc[jj][2] + bia0,
                                q1.y + Dm[jj][3] + Dc[jj][3] + bia1);
            }
        }
    }
    // ring landed long ago; make it (and MID, overlay safety) visible CTA-wide
    asm volatile("cp.async.wait_group 0;" ::: "memory");
    __syncthreads();

    // ---- Stage 2: wgt[64px][144] = mid @ W2 + b2  (3-term bf16 k16; wgt over W1) ----
    {
        const int m0 = (warp >> 2) * 16;
        const int nset = warp & 3;
        float Dm[5][4], Dc[5][4];
        #pragma unroll
        for (int j = 0; j < 5; j++)
            #pragma unroll
            for (int i = 0; i < 4; i++) { Dm[j][i] = 0.f; Dc[j][i] = 0.f; }

        #pragma unroll
        for (int k0 = 0; k0 < RED; k0 += 16) {
            float2 q0 = *(const float2*)(s + OFF_MID + (m0 + gid)     * MID_STRIDE + k0 + 2 * t4);
            float2 q1 = *(const float2*)(s + OFF_MID + (m0 + gid + 8) * MID_STRIDE + k0 + 2 * t4);
            float2 q2 = *(const float2*)(s + OFF_MID + (m0 + gid)     * MID_STRIDE + k0 + 8 + 2 * t4);
            float2 q3 = *(const float2*)(s + OFF_MID + (m0 + gid + 8) * MID_STRIDE + k0 + 8 + 2 * t4);
            uint32_t ah[4], al[4];
            bf16_split_pair(q0.x, q0.y, ah[0], al[0]);
            bf16_split_pair(q1.x, q1.y, ah[1], al[1]);
            bf16_split_pair(q2.x, q2.y, ah[2], al[2]);
            bf16_split_pair(q3.x, q3.y, ah[3], al[3]);
            const int kw = (k0 >> 1) + t4;
            #pragma unroll
            for (int jj = 0; jj < 5; jj++) {
                int j = nset + jj * 4;
                if (j < 18) {
                    int e = j * 8 + gid;
                    uint32_t bh0 = su[OFF_W2H + e * W2P_STRIDE + kw];
                    uint32_t bh1 = su[OFF_W2H + e * W2P_STRIDE + kw + 4];
                    uint32_t bl0 = su[OFF_W2L + e * W2P_STRIDE + kw];
                    uint32_t bl1 = su[OFF_W2L + e * W2P_STRIDE + kw + 4];
                    mma_bf16(Dm[jj], ah[0], ah[1], ah[2], ah[3], bh0, bh1);
                    mma_bf16(Dc[jj], al[0], al[1], al[2], al[3], bh0, bh1);
                    mma_bf16(Dc[jj], ah[0], ah[1], ah[2], ah[3], bl0, bl1);
                }
            }
        }
        #pragma unroll
        for (int jj = 0; jj < 5; jj++) {
            int j = nset + jj * 4;
            if (j < 18) {
                int e0 = j * 8 + 2 * t4;
                float bb0 = s[OFF_B2 + e0], bb1 = s[OFF_B2 + e0 + 1];
                s[OFF_WGT + (m0 + gid)     * WGT_STRIDE + e0]     = Dm[jj][0] + Dc[jj][0] + bb0;
                s[OFF_WGT + (m0 + gid)     * WGT_STRIDE + e0 + 1] = Dm[jj][1] + Dc[jj][1] + bb1;
                s[OFF_WGT + (m0 + gid + 8) * WGT_STRIDE + e0]     = Dm[jj][2] + Dc[jj][2] + bb0;
                s[OFF_WGT + (m0 + gid + 8) * WGT_STRIDE + e0 + 1] = Dm[jj][3] + Dc[jj][3] + bb1;
            }
        }
    }
    // per-HALF barrier: half A = warps 0-7 (m-tiles 0-1 -> rows 0-3),
    //                   half B = warps 8-15 (m-tiles 2-3 -> rows 4-7)
    asm volatile("bar.sync %0, 256;" :: "r"(1 + (warp >> 3)) : "memory");

    // ---- Stage 3: involution (remapped: half = warp>>3, gset = warp&7) ----
    {
        const int half = warp >> 3, gset = warp & 7;
        const int pr = half * 4 + (lane >> 3), pc = lane & 7;
        const int wbase = OFF_WGT + (pr * 8 + pc) * WGT_STRIDE;
        const int xb = OFF_XH + (pr * 10 + pc) * XH_STRIDE;   // tap (di=0,dj=0)
        float* op = out + ((size_t)((bb * HWDIM + h0 + pr) * HWDIM + (w0 + pc))) * CCH;
        #pragma unroll
        for (int gi = 0; gi < 2; gi++) {
            int g = gset * 2 + gi;
            float wv[9];
            #pragma unroll
            for (int k = 0; k < 9; k++) wv[k] = s[wbase + g * 9 + k];
            int F0g = g * 36;
            int ko0 = F0g >> 6;
            int cs0 = F0g & 63;
            int tc  = 64 - cs0;
            int di0 = (ko0 * 11) >> 5, dj0 = ko0 - 3 * di0;
            int ko1 = ko0 + 1;
            int di1 = (ko1 * 11) >> 5, dj1 = ko1 - 3 * di1;
            int A0 = xb + (di0 * 10 + dj0) * XH_STRIDE + cs0 * 4;
            int A1 = xb + (di1 * 10 + dj1) * XH_STRIDE - tc * 4;
            #pragma unroll
            for (int c = 0; c < 4; c++) {
                float acc[4] = {0.f, 0.f, 0.f, 0.f};
                #pragma unroll
                for (int j = 0; j < 9; j++) {
                    const int idx = c * 9 + j;
                    int addr = ((idx < tc) ? A0 : A1) + idx * 4;
                    const float4 xv = *(const float4*)(s + addr);
                    const int fl = idx * 4;
                    acc[(fl + 0) / 9 - c * 4] += wv[(fl + 0) % 9] * xv.x;
                    acc[(fl + 1) / 9 - c * 4] += wv[(fl + 1) % 9] * xv.y;
                    acc[(fl + 2) / 9 - c * 4] += wv[(fl + 2) % 9] * xv.z;
                    acc[(fl + 3) / 9 - c * 4] += wv[(fl + 3) % 9] * xv.w;
                }
                *(float4*)(op + g * 16 + c * 4) =
                    make_float4(acc[0], acc[1], acc[2], acc[3]);
            }
        }
    }
}

extern "C" void kernel_launch(void* const* d_in, const int* in_sizes, int n_in,
                              void* d_out, int out_size)
{
    (void)in_sizes; (void)n_in; (void)out_size;
    const float* x  = (const float*)d_in[0];
    const float* W1 = (const float*)d_in[1];
    const float* b1 = (const float*)d_in[2];
    const float* W2 = (const float*)d_in[3];
    const float* b2 = (const float*)d_in[4];
    float* out = (float*)d_out;

    cudaFuncSetAttribute(invo_mma_kernel,
                         cudaFuncAttributeMaxDynamicSharedMemorySize, SMEM_BYTES);
    dim3 grid(HWDIM / 8, HWDIM / 8, BATCH);   // (8, 8, 8) = 512 CTAs
    invo_mma_kernel<<<grid, NTHR, SMEM_BYTES>>>(x, W1, b1, W2, b2, out);
}